// round 7
// baseline (speedup 1.0000x reference)
#include <cuda_runtime.h>
#include <cooperative_groups.h>
#include <math.h>

namespace cg = cooperative_groups;

#define FEAT  52
#define NPIX  2704
#define NA    24336
#define NSORT 32768
#define PRE   12000
#define POST  2000
#define NCB   188
#define NGR   24          // ceil(PRE/512)

#define OUT_ROIS 0
#define OUT_LOCS 8000
#define OUT_CLS1 105344
#define OUT_OBJ  154016
#define OUT_CLS2 178352

#define SMEM_CONV ((256*3*28 + 64*64) * 4)   // 100KB -> 2 blocks/SM

// ---------------- device scratch (static, no allocs) ----------------
__device__ float  g_wt[2304 * 256];           // [(kh*3+kw)*256+ci][co]
__device__ float4 g_h4[NPIX * 64];            // conv1 output, [p][256]
__device__ float4 g_roi4[NA];
__device__ unsigned char g_valid[NA];
__device__ unsigned long long g_key[NSORT];
__device__ float4 g_sbox[PRE];
__device__ float  g_sarea[PRE];
__device__ unsigned long long g_rem0[NCB];
// NMS pipeline state
__device__ float4 g_kept_box[2560];
__device__ float  g_kept_area[2560];
__device__ int    g_nkept;
__device__ int    g_done;
__device__ unsigned long long g_csup[2][8];
__device__ unsigned long long g_gdiag[2][4096];   // [parity][r*8+w]

// ---------------- Cephes/Eigen-style expf ----------------------------------
__device__ __forceinline__ float cephes_expf(float x) {
    float m = floorf(fmaf(x, 1.44269504088896341f, 0.5f));
    float r = fmaf(m, -0.693359375f, x);
    r = fmaf(m, 2.12194440e-4f, r);
    float r2 = __fmul_rn(r, r);
    float y = 1.9875691500E-4f;
    y = fmaf(y, r, 1.3981999507E-3f);
    y = fmaf(y, r, 8.3334519073E-3f);
    y = fmaf(y, r, 4.1665795894E-2f);
    y = fmaf(y, r, 1.6666665459E-1f);
    y = fmaf(y, r, 5.0000001201E-1f);
    y = fmaf(y, r2, r);
    y = __fadd_rn(y, 1.0f);
    return ldexpf(y, (int)m);
}

// exact IoU>0.7 test (fast path + bit-exact div fallback in ambiguous band)
__device__ __forceinline__ bool iou_gt(float4 b, float ai, float4 c, float aj) {
    float yy1 = fmaxf(b.x, c.x), xx1 = fmaxf(b.y, c.y);
    float yy2 = fminf(b.z, c.z), xx2 = fminf(b.w, c.w);
    float dx = __fadd_rn(__fsub_rn(xx2, xx1), 1.f);
    float dy = __fadd_rn(__fsub_rn(yy2, yy1), 1.f);
    float inter = __fmul_rn(fmaxf(0.f, dx), fmaxf(0.f, dy));
    float denom = __fsub_rn(__fadd_rn(ai, aj), inter);
    float diff = __fsub_rn(inter, __fmul_rn(0.7f, denom));
    if (fabsf(diff) > 1e-5f * denom) return diff > 0.f;
    return __fdiv_rn(inter, denom) > 0.7f;
}

// ---------------- 1: weight transpose + zeroing + state init ---------------
__global__ void k_wt(const float* __restrict__ w, float* __restrict__ out) {
    int o = blockIdx.x * 256 + threadIdx.x;
    if (o < 2304 * 256) {
        int co  = o & 255;
        int k   = o >> 8;
        int ci  = k & 255;
        int khw = k >> 8;
        g_wt[o] = w[co * 2304 + ci * 9 + khw];
    }
    if (o < 8000) out[OUT_ROIS + o] = 0.f;
    if (o < NCB)  g_rem0[o] = 0ull;
    if (o < NSORT - NA) g_key[NA + o] = ~0ull;   // sort padding
    if (o == 0) { g_nkept = 0; g_done = 0; }
    if (o < 16) ((unsigned long long*)g_csup)[o] = 0ull;
}

// ---------------- 2: conv1 3x3 SAME 256->256, strict (kh,kw,ci) FMA chain --
// grid (4 cog, 104): y = by/2, xh = by&1 (26-px half-rows). 208 threads:
// quad = t&15 (4 co), pxg = t>>4 (2 px each, 13 groups)
__global__ __launch_bounds__(208) void k_conv(const float* __restrict__ x,
                                              const float* __restrict__ bias) {
    extern __shared__ float smem[];
    float* s_in = smem;                       // [ci*3+row][28]
    float* s_w  = smem + 256 * 3 * 28;        // [64 ci][64 co]
    int t = threadIdx.x;
    int cog = blockIdx.x;
    int y   = blockIdx.y >> 1;
    int xh  = blockIdx.y & 1;
    int quad = t & 15;
    int pxg  = t >> 4;

    float acc[4][2];
#pragma unroll
    for (int c = 0; c < 4; c++) { acc[c][0] = 0.f; acc[c][1] = 0.f; }

    // stage input: 256 ci x 3 rows x 28 cols (halo, zero-padded)
    for (int e = t; e < 256 * 3 * 28; e += 208) {
        int ci  = e / 84;
        int rem = e - ci * 84;
        int row = rem / 28;
        int col = rem - row * 28;
        int yy = y + row - 1;
        int xx = xh * 26 + col - 1;
        float v = 0.f;
        if ((unsigned)yy < 52u && (unsigned)xx < 52u)
            v = x[ci * NPIX + yy * 52 + xx];
        s_in[e] = v;
    }

    for (int khw = 0; khw < 9; khw++) {
        int kh = khw / 3, kw = khw - 3 * (khw / 3);
        for (int q = 0; q < 4; q++) {          // 64-ci quarters, ascending
            __syncthreads();
            for (int e = t; e < 4096; e += 208)
                s_w[e] = g_wt[((khw << 8) + (q << 6) + (e >> 6)) * 256 + cog * 64 + (e & 63)];
            __syncthreads();
            const float* ip = &s_in[(q * 64) * 84 + kh * 28 + pxg * 2 + kw];
#pragma unroll 8
            for (int ci = 0; ci < 64; ci++) {
                float v0 = ip[0], v1 = ip[1];
                const float4 wv = *(const float4*)&s_w[ci * 64 + quad * 4];
                acc[0][0] = fmaf(wv.x, v0, acc[0][0]);
                acc[0][1] = fmaf(wv.x, v1, acc[0][1]);
                acc[1][0] = fmaf(wv.y, v0, acc[1][0]);
                acc[1][1] = fmaf(wv.y, v1, acc[1][1]);
                acc[2][0] = fmaf(wv.z, v0, acc[2][0]);
                acc[2][1] = fmaf(wv.z, v1, acc[2][1]);
                acc[3][0] = fmaf(wv.w, v0, acc[3][0]);
                acc[3][1] = fmaf(wv.w, v1, acc[3][1]);
                ip += 84;
            }
        }
    }

    float* h = (float*)g_h4;
#pragma unroll
    for (int c = 0; c < 4; c++) {
        int co = cog * 64 + quad * 4 + c;
        float b = bias[co];
#pragma unroll
        for (int j = 0; j < 2; j++) {
            int px = xh * 26 + pxg * 2 + j;
            h[(y * 52 + px) * 256 + co] = __fadd_rn(acc[c][j], b);
        }
    }
}

// ---------------- 3: fused 1x1 heads + anchor decode + sort-key build ------
__global__ __launch_bounds__(216) void k_heads(const float* __restrict__ rw,
                                               const float* __restrict__ rb,
                                               const float* __restrict__ cw,
                                               const float* __restrict__ cbp,
                                               float* __restrict__ out) {
    __shared__ float s_h[4 * 256];
    __shared__ float s_w[54 * 129];
    __shared__ float s_res[4][56];
    int t = threadIdx.x;
    int pxb = blockIdx.x * 4;
    const float* h = (const float*)g_h4;
    for (int e = t; e < 1024; e += 216)
        s_h[e] = h[(size_t)pxb * 256 + e];

    int px = t / 54;
    int o  = t - px * 54;
    float acc = 0.f;
    for (int hs = 0; hs < 2; hs++) {
        __syncthreads();
        for (int e = t; e < 54 * 128; e += 216) {
            int oo = e >> 7, ci = e & 127;
            float wv = (oo < 36) ? rw[oo * 256 + hs * 128 + ci]
                                 : cw[(oo - 36) * 256 + hs * 128 + ci];
            s_w[oo * 129 + ci] = wv;
        }
        __syncthreads();
        const float* hp = &s_h[px * 256 + hs * 128];
        const float* wp = &s_w[o * 129];
#pragma unroll 8
        for (int ci = 0; ci < 128; ci++)
            acc = fmaf(wp[ci], hp[ci], acc);
    }
    int pg = pxb + px;
    float resv;
    if (o < 36) {
        resv = __fadd_rn(acc, __ldg(rb + o));
        out[OUT_LOCS + pg * 36 + o] = resv;
    } else {
        int oc = o - 36;
        resv = __fadd_rn(acc, __ldg(cbp + oc));
        out[OUT_CLS1 + pg * 18 + oc] = resv;
        out[OUT_CLS2 + pg * 18 + oc] = resv;
        if (oc & 1) out[OUT_OBJ + pg * 9 + (oc >> 1)] = resv;
    }
    s_res[px][o] = resv;
    __syncthreads();

    if (t < 36) {
        int px2 = t / 9, a = t - px2 * 9;
        int pg2 = pxb + px2;
        int i = pg2 * 9 + a;
        int ri = a / 3, si = a - ri * 3;
        double ratio = (ri == 0) ? 0.5 : (ri == 1 ? 1.0 : 2.0);
        double scale = (si == 0) ? 4.0 : (si == 1 ? 8.0 : 16.0);
        double hd = 4.0 * scale * sqrt(ratio);
        double wd = 4.0 * scale * sqrt(1.0 / ratio);
        double cyd = (double)(4 * (pg2 / 52) + 2);
        double cxd = (double)(4 * (pg2 % 52) + 2);
        float a0 = (float)(cyd - hd * 0.5);
        float a1 = (float)(cxd - wd * 0.5);
        float a2 = (float)(cyd + hd * 0.5);
        float a3 = (float)(cxd + wd * 0.5);

        float ah = __fsub_rn(a2, a0), aw = __fsub_rn(a3, a1);
        float acy = __fadd_rn(a0, __fmul_rn(0.5f, ah));
        float acx = __fadd_rn(a1, __fmul_rn(0.5f, aw));

        float l0 = s_res[px2][a * 4 + 0];
        float l1 = s_res[px2][a * 4 + 1];
        float l2 = s_res[px2][a * 4 + 2];
        float l3 = s_res[px2][a * 4 + 3];
        float s  = s_res[px2][36 + a * 2 + 1];

        float cy = __fadd_rn(__fmul_rn(l0, ah), acy);
        float cx = __fadd_rn(__fmul_rn(l1, aw), acx);
        float hh = __fmul_rn(cephes_expf(l2), ah);
        float ww = __fmul_rn(cephes_expf(l3), aw);
        float r0 = __fsub_rn(cy, __fmul_rn(0.5f, hh));
        float r1 = __fsub_rn(cx, __fmul_rn(0.5f, ww));
        float r2 = __fadd_rn(cy, __fmul_rn(0.5f, hh));
        float r3 = __fadd_rn(cx, __fmul_rn(0.5f, ww));
        r0 = fminf(fmaxf(r0, 0.f), 210.f);
        r1 = fminf(fmaxf(r1, 0.f), 210.f);
        r2 = fminf(fmaxf(r2, 0.f), 210.f);
        r3 = fminf(fmaxf(r3, 0.f), 210.f);
        float hs = __fsub_rn(r2, r0), ws = __fsub_rn(r3, r1);
        bool valid = (hs >= 16.f) && (ws >= 16.f);

        g_roi4[i] = make_float4(r0, r1, r2, r3);
        g_valid[i] = valid ? 1 : 0;

        float sm = valid ? s : __int_as_float(0xff800000);
        unsigned u = __float_as_uint(sm);
        u = (u & 0x80000000u) ? ~u : (u | 0x80000000u);
        g_key[i] = ((unsigned long long)(~u) << 32) | (unsigned long long)(unsigned)i;
    }
}

// ---------------- bitonic helpers ------------------------------------------
__device__ __forceinline__ void cswap(unsigned long long& a, unsigned long long& b, bool asc) {
    bool sw = asc ? (a > b) : (a < b);
    if (sw) { unsigned long long tt = a; a = b; b = tt; }
}

__device__ void bitonic_tile(unsigned long long* sk, int base, int t, int s, int jmax) {
    for (int j = jmax; j >= 1; j >>= 1) {
        __syncthreads();
#pragma unroll
        for (int q = 0; q < 2; q++) {
            int p = t + q * 1024;
            int i = 2 * p - (p & (j - 1));
            bool asc = (((base + i) & s) == 0);
            unsigned long long a = sk[i], b = sk[i + j];
            cswap(a, b, asc);
            sk[i] = a; sk[i + j] = b;
        }
    }
}

// ---------------- 4: cooperative tail: sort + gather + pipelined NMS -------
__global__ __launch_bounds__(1024, 1) void k_tail(float* __restrict__ out) {
    cg::grid_group grid = cg::this_grid();
    __shared__ unsigned long long s_buf[4096];   // sort tile / diag[512][8]
    __shared__ unsigned long long s_sup[8], s_kw[8];
    __shared__ int s_pref[9];

    int t  = threadIdx.x;
    int bx = blockIdx.x;
    int gtid = bx * 1024 + t;
    int gsz  = gridDim.x * 1024;

    // ---- sort: local full (blocks 0-7, 4096-element tiles) ----
    if (bx < 8) {
        int base = bx * 4096;
#pragma unroll
        for (int q = 0; q < 4; q++) s_buf[t + q * 1024] = g_key[base + t + q * 1024];
        for (int s = 2; s <= 4096; s <<= 1) bitonic_tile(s_buf, base, t, s, s >> 1);
        __syncthreads();
#pragma unroll
        for (int q = 0; q < 4; q++) g_key[base + t + q * 1024] = s_buf[t + q * 1024];
    }
    grid.sync();

    // ---- sort: global steps + local tails ----
#pragma unroll
    for (int si = 0; si < 3; si++) {
        int s = 8192 << si;
        for (int j = s >> 1; j >= 4096; j >>= 1) {
            if (gtid < 16384) {
                int p = gtid;
                int i = 2 * p - (p & (j - 1));
                bool asc = ((i & s) == 0);
                unsigned long long a = g_key[i], b = g_key[i + j];
                cswap(a, b, asc);
                g_key[i] = a; g_key[i + j] = b;
            }
            grid.sync();
        }
        if (bx < 8) {
            int base = bx * 4096;
#pragma unroll
            for (int q = 0; q < 4; q++) s_buf[t + q * 1024] = g_key[base + t + q * 1024];
            bitonic_tile(s_buf, base, t, s, 2048);
            __syncthreads();
#pragma unroll
            for (int q = 0; q < 4; q++) g_key[base + t + q * 1024] = s_buf[t + q * 1024];
        }
        grid.sync();
    }

    // ---- gather sorted boxes ----
    for (int i = gtid; i < PRE; i += gsz) {
        unsigned idx = (unsigned)(g_key[i] & 0xFFFFFFFFull);
        float4 b = g_roi4[idx];
        g_sbox[i] = b;
        g_sarea[i] = __fmul_rn(__fadd_rn(__fsub_rn(b.w, b.y), 1.f),
                               __fadd_rn(__fsub_rn(b.z, b.x), 1.f));
        if (!g_valid[idx]) atomicOr(&g_rem0[i >> 6], 1ull << (i & 63));
    }
    grid.sync();

    // ---- pre-compute diag(0) (all blocks) ----
    {
        int n_local = 512;
        for (int u = gtid; u < 4096; u += gsz) {
            int r = u >> 3, w = u & 7;
            unsigned long long bits = 0ull;
            if (r < n_local) {
                float4 bi = g_sbox[r]; float ai = g_sarea[r];
                int j0 = w * 64;
                int jlo = max(j0, r + 1), jhi = min(j0 + 64, n_local);
                for (int j = jlo; j < jhi; j++)
                    if (iou_gt(bi, ai, g_sbox[j], g_sarea[j])) bits |= 1ull << (j - j0);
            }
            g_gdiag[0][u] = bits;
        }
    }

    // ---- pipelined NMS loop: block0 resolves g; others prep g+1 ----
    int patch_lo = 0;
    for (int g = 0; g < NGR; g++) {
        grid.sync();
        if (*(volatile int*)&g_done) break;
        int nk_now = *(volatile int*)&g_nkept;
        int parity = g & 1;

        if (bx == 0) {
            // ------- resolve group g -------
            int base = g * 512;
            int n_local = min(512, PRE - base);
            // load diag to smem
            for (int e = t; e < 4096; e += 1024) s_buf[e] = g_gdiag[parity][e];
            // init suppression words
            if (t < 8) {
                int chunk = g * 8 + t;
                unsigned long long v = g_csup[parity][t];
                if (chunk < NCB) v |= g_rem0[chunk];
                int rem = n_local - t * 64;
                if (rem <= 0) v = ~0ull;
                else if (rem < 64) v |= ~((1ull << rem) - 1ull);
                s_sup[t] = v;
            }
            __syncthreads();
            // patch: candidates vs kept added during previous resolve
            int np = nk_now - patch_lo;
            for (int p = t; p < np * 512; p += 1024) {
                int k = patch_lo + (p >> 9), j = p & 511;
                if (j < n_local &&
                    iou_gt(g_kept_box[k], g_kept_area[k], g_sbox[base + j], g_sarea[base + j]))
                    atomicOr(&s_sup[j >> 6], 1ull << (j & 63));
            }
            __syncthreads();
            // word-walk resolve
            for (int w = 0; w < 8; w++) {
                if (t == 0) {
                    unsigned long long sup = s_sup[w];
                    unsigned long long kept = 0ull;
                    unsigned long long avail = ~sup;
                    while (avail) {
                        int i = __ffsll((long long)avail) - 1;
                        kept |= 1ull << i;
                        sup |= s_buf[(w * 64 + i) * 8 + w];
                        unsigned long long lm = (i == 63) ? ~0ull : ((2ull << i) - 1ull);
                        avail = ~sup & ~lm;
                    }
                    s_kw[w] = kept;
                }
                __syncthreads();
                if (t < 512) {
                    int i = t >> 3, w2 = t & 7;
                    if (w2 > w && ((s_kw[w] >> i) & 1ull))
                        atomicOr(&s_sup[w2], s_buf[(w * 64 + i) * 8 + w2]);
                }
                __syncthreads();
            }
            if (t == 0) {
                int pref = 0;
#pragma unroll
                for (int w = 0; w < 8; w++) { s_pref[w] = pref; pref += __popcll(s_kw[w]); }
                s_pref[8] = pref;
            }
            __syncthreads();
            if (t < 512) {
                int w = t >> 6, b = t & 63;
                unsigned long long kwv = s_kw[w];
                if ((kwv >> b) & 1ull) {
                    int pos = nk_now + s_pref[w] + __popcll(kwv & ((1ull << b) - 1ull));
                    float4 bxv = g_sbox[base + t];
                    if (pos < POST) {
                        out[OUT_ROIS + pos * 4 + 0] = bxv.x;
                        out[OUT_ROIS + pos * 4 + 1] = bxv.y;
                        out[OUT_ROIS + pos * 4 + 2] = bxv.z;
                        out[OUT_ROIS + pos * 4 + 3] = bxv.w;
                    }
                    if (pos < 2560) {
                        g_kept_box[pos]  = bxv;
                        g_kept_area[pos] = g_sarea[base + t];
                    }
                }
            }
            __syncthreads();
            if (t == 0) {
                int total = nk_now + s_pref[8];
                g_nkept = total;
                if (total >= POST) g_done = 1;
#pragma unroll
                for (int w = 0; w < 8; w++) g_csup[parity][w] = 0ull;
            }
        } else if (g + 1 < NGR) {
            // ------- prep group g+1 (blocks 1..147) -------
            int gg = g + 1;
            int base = gg * 512;
            int n_local = min(512, PRE - base);
            int pp = gg & 1;
            int gtid2 = (bx - 1) * 1024 + t;
            int gsz2  = (gridDim.x - 1) * 1024;
            // A: candidates vs all kept known so far
            for (int p = gtid2; p < nk_now * 512; p += gsz2) {
                int k = p >> 9, j = p & 511;
                if (j < n_local &&
                    iou_gt(g_kept_box[k], g_kept_area[k], g_sbox[base + j], g_sarea[base + j]))
                    atomicOr(&g_csup[pp][j >> 6], 1ull << (j & 63));
            }
            // diag
            for (int u = gtid2; u < 4096; u += gsz2) {
                int r = u >> 3, w = u & 7;
                unsigned long long bits = 0ull;
                if (r < n_local) {
                    float4 bi = g_sbox[base + r]; float ai = g_sarea[base + r];
                    int j0 = w * 64;
                    int jlo = max(j0, r + 1), jhi = min(j0 + 64, n_local);
                    for (int j = jlo; j < jhi; j++)
                        if (iou_gt(bi, ai, g_sbox[base + j], g_sarea[base + j]))
                            bits |= 1ull << (j - j0);
                }
                g_gdiag[pp][u] = bits;
            }
        }
        patch_lo = nk_now;
    }
}

// ---------------- launch ----------------------------------------------------
extern "C" void kernel_launch(void* const* d_in, const int* in_sizes, int n_in,
                              void* d_out, int out_size) {
    const float* x   = (const float*)d_in[0];
    const float* c1w = (const float*)d_in[1];
    const float* c1b = (const float*)d_in[2];
    const float* rw  = (const float*)d_in[3];
    const float* rb  = (const float*)d_in[4];
    const float* cw  = (const float*)d_in[5];
    const float* cb  = (const float*)d_in[6];
    float* out = (float*)d_out;

    cudaFuncSetAttribute(k_conv, cudaFuncAttributeMaxDynamicSharedMemorySize, SMEM_CONV);

    k_wt<<<2304, 256>>>(c1w, out);
    k_conv<<<dim3(4, 104), 208, SMEM_CONV>>>(x, c1b);
    k_heads<<<676, 216>>>(rw, rb, cw, cb, out);

    void* args[] = { (void*)&out };
    cudaLaunchCooperativeKernel((const void*)k_tail, dim3(148), dim3(1024),
                                args, 0, (cudaStream_t)0);
}